// round 7
// baseline (speedup 1.0000x reference)
#include <cuda_runtime.h>

#define B_ 256
#define T_ 1024
#define K_ 128
#define LN2 0.69314718055994531f

__device__ float g_logz[B_];
__device__ float g_gold[B_];

__device__ __forceinline__ void fma2(unsigned long long &acc, unsigned long long a, unsigned long long b) {
    asm("fma.rn.f32x2 %0, %1, %2, %0;" : "+l"(acc) : "l"(a), "l"(b));
}
__device__ __forceinline__ unsigned long long add2(unsigned long long a, unsigned long long b) {
    unsigned long long c;
    asm("add.rn.f32x2 %0, %1, %2;" : "=l"(c) : "l"(a), "l"(b));
    return c;
}
__device__ __forceinline__ unsigned long long pack2(float x, float y) {
    unsigned long long r;
    asm("mov.b64 %0, {%1, %2};" : "=l"(r) : "f"(x), "f"(y));
    return r;
}
__device__ __forceinline__ float2 unpack2(unsigned long long v) {
    float2 f;
    asm("mov.b64 {%0, %1}, %2;" : "=f"(f.x), "=f"(f.y) : "l"(v));
    return f;
}
__device__ __forceinline__ float warp_sum(float v) {
    #pragma unroll
    for (int o = 16; o > 0; o >>= 1) v += __shfl_xor_sync(0xffffffffu, v, o);
    return v;
}

// group barrier: 128 threads, barrier id 1 or 2 (uniform per group)
#define GBAR(gid) asm volatile("bar.sync %0, 128;" :: "r"(gid) : "memory")

// Forward logZ, exp domain, two INDEPENDENT 128-thread groups per CTA
// (one batch each) synchronized by named barriers, with a staggered start so
// the groups run anti-phased: one group's FMA burst overlaps the other's
// LDS/tail/barrier segment. Thread j of a group owns state j; E column in regs.
// Renorm is free: ke = exponent(p_prev[0]) peeked from the first GEMV load.
__global__ __launch_bounds__(256, 1) void crf_fwd(
    const float* __restrict__ emis,   // (B,T,K)
    const int* __restrict__ mask,     // (B,T) int32
    const float* __restrict__ start,  // (K)
    const float* __restrict__ endv,   // (K)
    const float* __restrict__ trans)  // (K,K)
{
    const int grp = threadIdx.x >> 7;         // 0 or 1
    const int j   = threadIdx.x & (K_ - 1);   // state
    const int b   = blockIdx.x * 2 + grp;
    const int bid = grp + 1;                  // named barrier id

    __shared__ __align__(16) float pbuf[2][2][K_];  // [grp][pingpong][state]
    __shared__ float wred[2][4];

    // E[:,j] packed over i-pairs
    unsigned long long e2[K_ / 2];
    #pragma unroll
    for (int k = 0; k < K_ / 2; ++k) {
        float ea  = __expf(trans[(2 * k) * K_ + j]);
        float ebv = __expf(trans[(2 * k + 1) * K_ + j]);
        e2[k] = pack2(ea, ebv);
    }

    const float* __restrict__ eb = emis + (size_t)b * T_ * K_;
    const int* __restrict__ mb = mask + (size_t)b * T_;

    float p = __expf(start[j] + eb[j]);  // t = 0
    int kacc = 0;
    pbuf[grp][0][j] = p;

    // 3-deep prefetch of exp(em) and mask
    float eA = __expf(eb[1 * K_ + j]);
    float eB = __expf(eb[2 * K_ + j]);
    float eC = __expf(eb[3 * K_ + j]);
    int mA = mb[1], mB = mb[2], mC = mb[3];

    // stagger group 1 by ~320 cycles (80-deep dependent FADD chain) so the
    // two groups run anti-phased; offset persists since step durations match.
    if (grp) {
        float x = p;
        #pragma unroll
        for (int d = 0; d < 80; ++d)
            asm volatile("add.f32 %0, %0, 0f3F800000;" : "+f"(x));
        // never true; keeps x live without affecting results
        if (__float_as_uint(x) == 0xDEADBEEFu) pbuf[grp][0][j] = x;
    }
    GBAR(bid);

    float* __restrict__ pb0 = pbuf[grp][0];
    float* __restrict__ pb1 = pbuf[grp][1];

#define CRF_STEP(T_IDX, PRD, PWR)                                             \
    {                                                                         \
        const int t_ = (T_IDX);                                               \
        float eem = eA; eA = eB; eB = eC;                                     \
        int mk = mA; mA = mB; mB = mC;                                        \
        if (t_ + 3 < T_) {                                                    \
            eC = __expf(eb[(size_t)(t_ + 3) * K_ + j]);                       \
            mC = mb[t_ + 3];                                                  \
        }                                                                     \
        const ulonglong2* __restrict__ pv = (const ulonglong2*)(PRD);         \
        ulonglong2 q0 = pv[0];                                                \
        float2 f0 = unpack2(q0.x);                                            \
        unsigned int xb = __float_as_uint(f0.x) >> 23;                        \
        int ke = (int)xb - 127;                                               \
        float scale = __uint_as_float((254u - xb) << 23);  /* 2^-ke exact */  \
        if (!mk) { ke = 0; scale = 1.0f; }                                    \
        float eemx = eem * scale;                                             \
        kacc += ke;                                                           \
        unsigned long long a0 = 0ull, a1 = 0ull, a2 = 0ull, a3 = 0ull;        \
        unsigned long long a4 = 0ull, a5 = 0ull, a6 = 0ull, a7 = 0ull;        \
        ulonglong2 q1 = pv[1];                                                \
        ulonglong2 q2 = pv[2];                                                \
        ulonglong2 q3 = pv[3];                                                \
        fma2(a0, q0.x, e2[0]); fma2(a1, q0.y, e2[1]);                         \
        fma2(a2, q1.x, e2[2]); fma2(a3, q1.y, e2[3]);                         \
        fma2(a4, q2.x, e2[4]); fma2(a5, q2.y, e2[5]);                         \
        fma2(a6, q3.x, e2[6]); fma2(a7, q3.y, e2[7]);                         \
        _Pragma("unroll")                                                     \
        for (int k = 1; k < 8; ++k) {                                         \
            ulonglong2 r0 = pv[4 * k];                                        \
            ulonglong2 r1 = pv[4 * k + 1];                                    \
            ulonglong2 r2 = pv[4 * k + 2];                                    \
            ulonglong2 r3 = pv[4 * k + 3];                                    \
            fma2(a0, r0.x, e2[8 * k]);     fma2(a1, r0.y, e2[8 * k + 1]);     \
            fma2(a2, r1.x, e2[8 * k + 2]); fma2(a3, r1.y, e2[8 * k + 3]);     \
            fma2(a4, r2.x, e2[8 * k + 4]); fma2(a5, r2.y, e2[8 * k + 5]);     \
            fma2(a6, r3.x, e2[8 * k + 6]); fma2(a7, r3.y, e2[8 * k + 7]);     \
        }                                                                     \
        a0 = add2(a0, a1); a2 = add2(a2, a3);                                 \
        a4 = add2(a4, a5); a6 = add2(a6, a7);                                 \
        a0 = add2(a0, a2); a4 = add2(a4, a6);                                 \
        a0 = add2(a0, a4);                                                    \
        float2 sp = unpack2(a0);                                              \
        float s = sp.x + sp.y;                                                \
        p = mk ? s * eemx : p;                                                \
        (PWR)[j] = p;                                                         \
        GBAR(bid);                                                            \
    }

    // 1023 steps: 511 unrolled pairs + 1 tail
    for (int t = 1; t < T_ - 1; t += 2) {
        CRF_STEP(t,     pb0, pb1)
        CRF_STEP(t + 1, pb1, pb0)
    }
    CRF_STEP(T_ - 1, pb0, pb1)
#undef CRF_STEP

    // logZ = ln2*kacc + log(sum_j p_j * exp(end_j)), per group
    float v = p * __expf(endv[j]);
    float ws = warp_sum(v);
    if ((j & 31) == 0) wred[grp][j >> 5] = ws;
    GBAR(bid);
    if (j == 0) {
        float sm = (wred[grp][0] + wred[grp][1]) + (wred[grp][2] + wred[grp][3]);
        g_logz[b] = LN2 * (float)kacc + __logf(sm);
    }
}

// Gold path score: one batch per CTA of 128 threads, strided over t.
__global__ void crf_gold(
    const float* __restrict__ emis,
    const int* __restrict__ tags,
    const int* __restrict__ mask,
    const float* __restrict__ start,
    const float* __restrict__ endv,
    const float* __restrict__ trans)
{
    const int b = blockIdx.x;
    const int tid = threadIdx.x;
    const float* __restrict__ eb = emis + (size_t)b * T_ * K_;
    const int* __restrict__ tg = tags + (size_t)b * T_;
    const int* __restrict__ mb = mask + (size_t)b * T_;

    float sc = 0.0f;
    int cnt = 0;
    for (int t = tid; t < T_; t += 128) {
        int mt = mb[t];
        cnt += mt ? 1 : 0;
        if (t >= 1 && mt && mb[t - 1]) {
            int pr = tg[t - 1]; pr = pr < 0 ? 0 : pr;
            int cr = tg[t];     cr = cr < 0 ? 0 : cr;
            sc += trans[pr * K_ + cr] + eb[(size_t)t * K_ + cr];
        }
    }

    __shared__ float wsc[4];
    __shared__ int wcn[4];
    float s = warp_sum(sc);
    int c = cnt;
    #pragma unroll
    for (int o = 16; o > 0; o >>= 1) c += __shfl_xor_sync(0xffffffffu, c, o);
    if ((tid & 31) == 0) { wsc[tid >> 5] = s; wcn[tid >> 5] = c; }
    __syncthreads();
    if (tid == 0) {
        float total = (wsc[0] + wsc[1]) + (wsc[2] + wsc[3]);
        int ctot = wcn[0] + wcn[1] + wcn[2] + wcn[3];
        int t0 = tg[0];
        float sc0 = (start[t0] + eb[t0]) * (mb[0] ? 1.0f : 0.0f);
        int lenm1 = ctot - 1;
        int last = tg[lenm1];
        g_gold[b] = total + sc0 + endv[last];
    }
}

// Final: mean over batches of (logZ - gold), fixed-order tree reduction.
__global__ void crf_finish(float* __restrict__ out) {
    __shared__ float sm[B_];
    int i = threadIdx.x;
    sm[i] = g_logz[i] - g_gold[i];
    __syncthreads();
    #pragma unroll
    for (int s = 128; s > 0; s >>= 1) {
        if (i < s) sm[i] += sm[i + s];
        __syncthreads();
    }
    if (i == 0) out[0] = sm[0] * (1.0f / B_);
}

extern "C" void kernel_launch(void* const* d_in, const int* in_sizes, int n_in,
                              void* d_out, int out_size) {
    const float* emis   = (const float*)d_in[0];
    const int* tags     = (const int*)d_in[1];
    const int* mask     = (const int*)d_in[2];
    const float* start  = (const float*)d_in[3];
    const float* endv   = (const float*)d_in[4];
    const float* trans  = (const float*)d_in[5];
    float* out = (float*)d_out;

    crf_fwd<<<B_ / 2, 256>>>(emis, mask, start, endv, trans);
    crf_gold<<<B_, K_>>>(emis, tags, mask, start, endv, trans);
    crf_finish<<<1, B_>>>(out);
}